// round 5
// baseline (speedup 1.0000x reference)
#include <cuda_runtime.h>
#include <cuda_bf16.h>
#include <math.h>
#include <stdint.h>

// ContrastiveLoss: loss = sum_i [ logsumexp_j(X_i.Y_j/T) - X_i.Y_i/T ]
// N=8192, C=512, T=0.07. tf32 mma.sync, fragment-major prepacked operands,
// 64x64 warp tiles, race-free 3-stage cp.async pipeline, fused online LSE.

#define NTOT 8192
#define CDIM 512
#define ROWB 128
#define COLSPLIT 4
#define COLS_PER_SPLIT (NTOT / COLSPLIT)   // 2048
#define TILE_N 256
#define NTILES (COLS_PER_SPLIT / TILE_N)   // 8
#define NSTEPS (NTILES * 16)               // 128 (step = one 32-wide k chunk)
#define NPART  (COLSPLIT * 4)              // 16

#define XSTAGE_BYTES 16384                 // 128 rows x 32 k x 4B
#define YSTAGE_BYTES 32768                 // 256 cols x 32 k x 4B
#define STAGE_BYTES  (XSTAGE_BYTES + YSTAGE_BYTES)
#define NSTAGE 3
#define SMEM_TOTAL (NSTAGE * STAGE_BYTES)  // 147456

#define PLANE_FLOATS 262144                // floats per k-chunk plane

#define SCALE_LOG2 (14.285714285714286f * 1.4426950408889634f)
#define LN2 0.6931471805599453f

// -------- scratch (device globals; no allocation allowed) --------
__device__ __align__(16) float g_Xa[NTOT * CDIM];   // A-fragment-major, tf32-rounded
__device__ __align__(16) float g_Yb[NTOT * CDIM];   // B-fragment-major, tf32-rounded
__device__ float g_m[NPART][NTOT];
__device__ float g_l[NPART][NTOT];
__device__ float g_pos[NTOT];
__device__ float g_row[NTOT];

__device__ __forceinline__ float ex2f(float x) {
    float y; asm("ex2.approx.ftz.f32 %0, %1;" : "=f"(y) : "f"(x)); return y;
}
__device__ __forceinline__ uint32_t smem_to_u32(const void* p) {
    uint32_t a;
    asm("{ .reg .u64 t; cvta.to.shared.u64 t, %1; cvt.u32.u64 %0, t; }" : "=r"(a) : "l"(p));
    return a;
}
__device__ __forceinline__ void cp_async16(uint32_t dst, const void* src) {
    asm volatile("cp.async.ca.shared.global [%0], [%1], 16;" :: "r"(dst), "l"(src) : "memory");
}
#define CP_COMMIT() asm volatile("cp.async.commit_group;" ::: "memory")
#define CP_WAIT_1() asm volatile("cp.async.wait_group 1;" ::: "memory")

__device__ __forceinline__ uint32_t tf32r(float x) {
    uint32_t r; asm("cvt.rna.tf32.f32 %0, %1;" : "=r"(r) : "f"(x)); return r;
}

__device__ __forceinline__ void mma_tf32(float* c, const uint4 a, uint32_t b0, uint32_t b1) {
    asm volatile(
        "mma.sync.aligned.m16n8k8.row.col.f32.tf32.tf32.f32 "
        "{%0,%1,%2,%3}, {%4,%5,%6,%7}, {%8,%9}, {%0,%1,%2,%3};"
        : "+f"(c[0]), "+f"(c[1]), "+f"(c[2]), "+f"(c[3])
        : "r"(a.x), "r"(a.y), "r"(a.z), "r"(a.w), "r"(b0), "r"(b1));
}

// -------- pre-kernel: tf32 round + fragment-major packing (unchanged) --------
__global__ void __launch_bounds__(256)
cl_pre_kernel(const float* __restrict__ X, const float* __restrict__ Y) {
    const uint32_t gid = blockIdx.x * 256u + threadIdx.x;
    const uint32_t NFRAG = (NTOT * CDIM) / 4;
    if (gid < NFRAG) {
        const uint32_t fid = gid;
        const uint32_t lane = fid & 31, s = (fid >> 5) & 3, rb = (fid >> 7) & 511, kc = fid >> 16;
        const uint32_t g = lane >> 2, q = lane & 3;
        const size_t base = (size_t)(rb * 16 + g) * CDIM + kc * 32 + s * 8 + q;
        uint4 o;
        o.x = tf32r(X[base]);
        o.y = tf32r(X[base + 8 * CDIM]);
        o.z = tf32r(X[base + 4]);
        o.w = tf32r(X[base + 8 * CDIM + 4]);
        *reinterpret_cast<uint4*>(g_Xa + (size_t)fid * 4) = o;
    } else {
        const uint32_t fid = gid - NFRAG;
        const uint32_t lane = fid & 31, kp = (fid >> 5) & 1, cb = (fid >> 6) & 1023, kc = fid >> 16;
        const uint32_t g = lane >> 2, q = lane & 3;
        const size_t base = (size_t)(cb * 8 + g) * CDIM + kc * 32 + kp * 16 + q;
        uint4 o;
        o.x = tf32r(Y[base]);
        o.y = tf32r(Y[base + 4]);
        o.z = tf32r(Y[base + 8]);
        o.w = tf32r(Y[base + 12]);
        *reinterpret_cast<uint4*>(g_Yb + (size_t)fid * 4) = o;
    }
}

// -------- main kernel --------
__global__ void __launch_bounds__(256, 1)
cl_mma_kernel() {
    extern __shared__ __align__(16) char smem[];
    const uint32_t sb = smem_to_u32(smem);
    const uint4* sm4 = reinterpret_cast<const uint4*>(smem);

    const int tid = threadIdx.x;
    const int wid = tid >> 5;
    const int lane = tid & 31;
    const int g = lane >> 2;
    const int q = lane & 3;
    const int warpM = wid >> 2;       // 0..1  (64-row half)
    const int warpN = wid & 3;        // 0..3  (64-col stripe)

    const int rowblk = blockIdx.x >> 2;
    const int split = blockIdx.x & 3;
    const int row0 = rowblk * ROWB;
    const int colbase = split * COLS_PER_SPLIT;

    // stage loader: step -> (tile t, k-chunk kc); X 4 + Y 8 cp.async per thread
    auto load_stage = [&](int step, int buf) {
        if (step < NSTEPS) {
            const int t = step >> 4;
            const int kc = step & 15;
            const float* xsrc = g_Xa + (size_t)kc * PLANE_FLOATS + (size_t)(row0 >> 4) * 512;
            const float* ysrc = g_Yb + (size_t)kc * PLANE_FLOATS
                                + (size_t)((colbase + t * TILE_N) >> 3) * 256;
            const uint32_t xd = sb + buf * STAGE_BYTES;
            const uint32_t yd = xd + XSTAGE_BYTES;
#pragma unroll
            for (int i = 0; i < 4; i++) {
                const int c = tid + i * 256;       // 0..1023
                cp_async16(xd + c * 16, xsrc + c * 4);
            }
#pragma unroll
            for (int i = 0; i < 8; i++) {
                const int c = tid + i * 256;       // 0..2047
                cp_async16(yd + c * 16, ysrc + c * 4);
            }
        }
        CP_COMMIT();
    };

    float acc[4][8][4];
    float m[8], l[8];
#pragma unroll
    for (int r = 0; r < 8; r++) { m[r] = -INFINITY; l[r] = 0.0f; }

    load_stage(0, 0);
    load_stage(1, 1);

    for (int step = 0; step < NSTEPS; step++) {
        const int buf = step % NSTAGE;

        if ((step & 15) == 0) {
#pragma unroll
            for (int mb = 0; mb < 4; mb++)
#pragma unroll
                for (int nb = 0; nb < 8; nb++)
#pragma unroll
                    for (int c = 0; c < 4; c++) acc[mb][nb][c] = 0.0f;
        }

        // race-free ordering: wait(stage step) -> barrier -> issue(step+2)
        CP_WAIT_1();
        __syncthreads();
        load_stage(step + 2, (step + 2) % NSTAGE);

        const uint4* Xf = sm4 + (buf * STAGE_BYTES) / 16;   // [rb(8)][s(4)][lane]
        const uint4* Yf = Xf + XSTAGE_BYTES / 16;           // [cb(32)][kp(2)][lane]

#pragma unroll
        for (int kp = 0; kp < 2; kp++) {
            uint4 bq[8];
#pragma unroll
            for (int nb = 0; nb < 8; nb++)
                bq[nb] = Yf[((warpN * 8 + nb) * 2 + kp) * 32 + lane];
#pragma unroll
            for (int ss = 0; ss < 2; ss++) {
                const int s = kp * 2 + ss;
#pragma unroll
                for (int mb = 0; mb < 4; mb++) {
                    const uint4 av = Xf[((warpM * 4 + mb) * 4 + s) * 32 + lane];
#pragma unroll
                    for (int nb = 0; nb < 8; nb++) {
                        if (ss == 0) mma_tf32(acc[mb][nb], av, bq[nb].x, bq[nb].y);
                        else         mma_tf32(acc[mb][nb], av, bq[nb].z, bq[nb].w);
                    }
                }
            }
        }

        // fused epilogue at tile end (register-only)
        if ((step & 15) == 15) {
            const int t = step >> 4;
            const int col0 = colbase + t * TILE_N + warpN * 64;
#pragma unroll
            for (int mb = 0; mb < 4; mb++) {
#pragma unroll
                for (int pr = 0; pr < 2; pr++) {
                    const int ri = mb * 2 + pr;
                    const int grow = row0 + warpM * 64 + mb * 16 + pr * 8 + g;
                    float v[16];
                    float tmax = -INFINITY;
#pragma unroll
                    for (int nb = 0; nb < 8; nb++) {
                        v[2 * nb] = acc[mb][nb][2 * pr] * SCALE_LOG2;
                        v[2 * nb + 1] = acc[mb][nb][2 * pr + 1] * SCALE_LOG2;
                        tmax = fmaxf(tmax, fmaxf(v[2 * nb], v[2 * nb + 1]));
                    }
                    tmax = fmaxf(tmax, __shfl_xor_sync(0xffffffffu, tmax, 1));
                    tmax = fmaxf(tmax, __shfl_xor_sync(0xffffffffu, tmax, 2));
                    const float nm = fmaxf(m[ri], tmax);
                    float sum = 0.0f;
#pragma unroll
                    for (int nb = 0; nb < 8; nb++) {
                        const int gc = col0 + nb * 8 + q * 2;
                        sum += ex2f(v[2 * nb] - nm) + ex2f(v[2 * nb + 1] - nm);
                        if (gc == grow) g_pos[grow] = v[2 * nb];
                        if (gc + 1 == grow) g_pos[grow] = v[2 * nb + 1];
                    }
                    sum += __shfl_xor_sync(0xffffffffu, sum, 1);
                    sum += __shfl_xor_sync(0xffffffffu, sum, 2);
                    l[ri] = l[ri] * ex2f(m[ri] - nm) + sum;
                    m[ri] = nm;
                }
            }
        }
    }

    if (q == 0) {
        const int sp = split * 4 + warpN;
#pragma unroll
        for (int mb = 0; mb < 4; mb++)
#pragma unroll
            for (int pr = 0; pr < 2; pr++) {
                const int grow = row0 + warpM * 64 + mb * 16 + pr * 8 + g;
                g_m[sp][grow] = m[mb * 2 + pr];
                g_l[sp][grow] = l[mb * 2 + pr];
            }
    }
}

// -------- combine + reduce --------
__global__ void cl_combine_kernel() {
    const int i = blockIdx.x * blockDim.x + threadIdx.x;
    if (i >= NTOT) return;
    float M = g_m[0][i];
#pragma unroll
    for (int s = 1; s < NPART; s++) M = fmaxf(M, g_m[s][i]);
    float L = 0.0f;
#pragma unroll
    for (int s = 0; s < NPART; s++) L += g_l[s][i] * ex2f(g_m[s][i] - M);
    g_row[i] = M + __log2f(L) - g_pos[i];
}

__global__ void cl_reduce_kernel(float* __restrict__ out) {
    __shared__ float sh[256];
    float s = 0.0f;
    for (int i = threadIdx.x; i < NTOT; i += 256) s += g_row[i];
    sh[threadIdx.x] = s;
    __syncthreads();
    for (int o = 128; o > 0; o >>= 1) {
        if (threadIdx.x < o) sh[threadIdx.x] += sh[threadIdx.x + o];
        __syncthreads();
    }
    if (threadIdx.x == 0) out[0] = sh[0] * LN2;
}

extern "C" void kernel_launch(void* const* d_in, const int* in_sizes, int n_in,
                              void* d_out, int out_size) {
    const float* X = (const float*)d_in[0];
    const float* Y = (const float*)d_in[1];
    float* out = (float*)d_out;

    cudaFuncSetAttribute(cl_mma_kernel, cudaFuncAttributeMaxDynamicSharedMemorySize, SMEM_TOTAL);

    cl_pre_kernel<<<(2 * (NTOT * CDIM) / 4) / 256, 256>>>(X, Y);
    cl_mma_kernel<<<64 * COLSPLIT, 256, SMEM_TOTAL>>>();
    cl_combine_kernel<<<NTOT / 256, 256>>>();
    cl_reduce_kernel<<<1, 256>>>(out);
}